// round 14
// baseline (speedup 1.0000x reference)
#include <cuda_runtime.h>

#define T_ 512
#define K_ 8
#define D_ 8
#define CP_ 28
#define BMAX 4096

#define NTHR 128
#define NPAIR 3
#define BTILE (NTHR * 2 * NPAIR)   // 768 b per block

typedef unsigned long long ull;

// ---------------- static scratch ----------------
__device__ ull        g_qT[T_ * K_ * D_ * D_];   // pair-dup, transposed: [(t,k)][j][i]
__device__ ulonglong2 g_cn[T_ * K_ * D_];        // (.x = dup cq, .y = dup nc)
__device__ ull        g_w2[T_ * K_];             // dup softmax weight
__device__ float      g_outT[(size_t)T_ * BMAX]; // transposed output staging

__device__ __forceinline__ float ex2f(float x) {
    float r; asm("ex2.approx.ftz.f32 %0, %1;" : "=f"(r) : "f"(x)); return r;
}
__device__ __forceinline__ ull fma2(ull a, ull b, ull c) {
    ull d; asm("fma.rn.f32x2 %0, %1, %2, %3;" : "=l"(d) : "l"(a), "l"(b), "l"(c)); return d;
}
__device__ __forceinline__ ull mul2(ull a, ull b) {
    ull d; asm("mul.rn.f32x2 %0, %1, %2;" : "=l"(d) : "l"(a), "l"(b)); return d;
}
__device__ __forceinline__ ull pack2(float lo, float hi) {
    ull r; asm("mov.b64 %0, {%1, %2};" : "=l"(r) : "f"(lo), "f"(hi)); return r;
}
__device__ __forceinline__ void unpack2(ull v, float& lo, float& hi) {
    asm("mov.b64 {%0, %1}, %2;" : "=f"(lo), "=f"(hi) : "l"(v));
}
__device__ __forceinline__ unsigned smem_u32(const void* p) {
    unsigned a;
    asm("{ .reg .u64 t; cvta.to.shared.u64 t, %1; cvt.u32.u64 %0, t; }" : "=r"(a) : "l"(p));
    return a;
}

// ---------------- fused precompute: Cayley + scaling + centers + softmax ----------------
// 8 threads per (t,k); thread j owns column j of the Gauss-Jordan pair [N|P],
// N=I-A, P=I+A  ->  P becomes Q^T  (Q = (I-A)(I+A)^{-1}).  No pivoting needed.
__global__ void __launch_bounds__(256) prep_kernel(const float* __restrict__ cov,
                                                   const float* __restrict__ centers,
                                                   const float* __restrict__ wlog,
                                                   const float* __restrict__ lvar) {
    const unsigned FULL = 0xffffffffu;
    int gid = blockIdx.x * 32 + (threadIdx.x >> 3);   // matrix index (t*8+k), exact 4096
    int j   = threadIdx.x & 7;                        // owned column
    const float* v = cov + gid * CP_;

    float N[D_], P[D_];
#pragma unroll
    for (int i = 0; i < D_; i++) {
        float a = 0.f;
        if (i != j) {
            int lo = i < j ? i : j, hi = i < j ? j : i;
            int m = lo * 8 + hi;
            float val = (m < CP_) ? v[m] : v[55 - m];
            a = (j > i) ? -0.5f * val : 0.5f * val;
        }
        float d = (i == j) ? 1.f : 0.f;
        N[i] = d - a;
        P[i] = d + a;
    }

#pragma unroll
    for (int c = 0; c < D_; c++) {
        float ncc = __shfl_sync(FULL, N[c], c, 8);
        float piv = 1.0f / ncc;
        N[c] *= piv;  P[c] *= piv;
#pragma unroll
        for (int r = 0; r < D_; r++) {
            if (r == c) continue;
            float f = __shfl_sync(FULL, N[r], c, 8);   // N[r][c], held by lane c
            N[r] = fmaf(-f, N[c], N[r]);
            P[r] = fmaf(-f, P[c], P[r]);
        }
    }
    // thread j holds P[r] = Q^T[r][j] = Q[j][r]

    float lv     = fminf(fmaxf(lvar[gid * D_ + j], -3.5f), 3.5f);
    float s_own  = sqrtf(0.72134752044448169f * expf(-lv));   // sqrt(0.5*log2e/var)
    float nc_own = rsqrtf(6.283185307179586f * expf(lv));

    float s_all[D_];
#pragma unroll
    for (int r = 0; r < D_; r++) s_all[r] = __shfl_sync(FULL, s_own, r, 8);

    float ce = centers[gid * D_ + j];
    float qs[D_], part[D_];
#pragma unroll
    for (int r = 0; r < D_; r++) {
        qs[r]   = P[r] * s_all[r];      // q_scaled[i=j][col=r]
        part[r] = ce * qs[r];
    }
#pragma unroll
    for (int off = 1; off < 8; off <<= 1)
#pragma unroll
        for (int r = 0; r < D_; r++)
            part[r] += __shfl_xor_sync(FULL, part[r], off, 8);

    // transposed store: g_qT[gid][col=r][i=j] = qs[r]
#pragma unroll
    for (int r = 0; r < D_; r++)
        g_qT[gid * (D_ * D_) + r * D_ + j] = pack2(qs[r], qs[r]);

    g_cn[gid * D_ + j] = make_ulonglong2(pack2(-part[j], -part[j]),
                                         pack2(nc_own, nc_own));

    if (j == 0) {
        int t = gid >> 3;
        float num = expf(fminf(fmaxf(wlog[gid], -3.5f), 3.5f));
        float den = 0.f;
#pragma unroll
        for (int k = 0; k < K_; k++)
            den += expf(fminf(fmaxf(wlog[t * K_ + k], -3.5f), 3.5f));
        float w = num / den;
        g_w2[gid] = pack2(w, w);
    }
}

// ---------------- main evaluation ----------------
// p[b,t] = sum_k w_k * prod_d (nc_d * 2^{-y_d^2} + EPS)
// x staged via cp.async.bulk (TMA pipe, off the L1 wavefront path);
// output written transposed (coalesced) to g_outT.
__global__ void __launch_bounds__(NTHR, 6) pdf_kernel(const float* __restrict__ x,
                                                      int B) {
    const int t   = blockIdx.y;
    const int tid = threadIdx.x;

    __shared__ __align__(16) float s_x[BTILE * D_];   // 24 KB
    __shared__ ulonglong2 s_q [K_ * D_ * D_ / 2];     // 4 KB
    __shared__ ulonglong2 s_cn[K_ * D_];              // 1 KB
    __shared__ ull        s_w [K_];
    __shared__ __align__(8) ull s_mbar;

    const int b0    = blockIdx.x * BTILE;
    const int valid = min(BTILE, B - b0);

    const unsigned mbar = smem_u32(&s_mbar);
    if (tid == 0)
        asm volatile("mbarrier.init.shared.b64 [%0], %1;" :: "r"(mbar), "r"(1) : "memory");

    // params GMEM -> SMEM (ordered by the syncthreads below)
    {
        const ulonglong2* gq = reinterpret_cast<const ulonglong2*>(g_qT) + (size_t)t * 256;
        s_q[tid]       = gq[tid];
        s_q[tid + 128] = gq[tid + 128];
        if (tid < 64) s_cn[tid] = g_cn[t * 64 + tid];
        else if (tid < 72) s_w[tid - 64] = g_w2[t * K_ + (tid - 64)];
    }
    __syncthreads();   // mbar init visible + params visible

    if (tid == 0)
        asm volatile("mbarrier.arrive.expect_tx.shared.b64 _, [%0], %1;"
                     :: "r"(mbar), "r"(32u * (unsigned)valid) : "memory");

    // each thread issues up to 6 bulk copies of one 32B x-row each
#pragma unroll
    for (int i = 0; i < 2 * NPAIR; i++) {
        int r = tid + i * NTHR;
        if (r < valid) {
            unsigned dst = smem_u32(s_x) + (unsigned)(r * 32);
            const void* src = (const char*)x + ((size_t)(b0 + r) * T_ + t) * 32;
            asm volatile("cp.async.bulk.shared::cluster.global.mbarrier::complete_tx::bytes "
                         "[%0], [%1], %2, [%3];"
                         :: "r"(dst), "l"(src), "r"(32u), "r"(mbar) : "memory");
        }
    }

    // wait for all copies (phase 0)
    {
        unsigned done;
        asm volatile("{\n\t.reg .pred p;\n\t"
                     "mbarrier.try_wait.parity.acquire.cta.shared::cta.b64 p, [%1], 0;\n\t"
                     "selp.b32 %0, 1, 0, p;\n\t}"
                     : "=r"(done) : "r"(mbar) : "memory");
        if (!done) {
            asm volatile("{\n\t.reg .pred P1;\n\t"
                         "WL_%=:\n\t"
                         "mbarrier.try_wait.parity.acquire.cta.shared::cta.b64 P1, [%0], 0, 0x989680;\n\t"
                         "@P1 bra.uni WD_%=;\n\t"
                         "bra.uni WL_%=;\n\t"
                         "WD_%=:\n\t}"
                         :: "r"(mbar) : "memory");
        }
    }

    // fill x registers from shared; pair u = rows tid+(2u)*NTHR (lo) and +NTHR (hi)
    ull xp[NPAIR][D_];
#pragma unroll
    for (int u = 0; u < NPAIR; u++) {
        int rl = tid + (2 * u) * NTHR, rh = rl + NTHR;
        const float4* pl = reinterpret_cast<const float4*>(s_x + rl * D_);
        const float4* ph = reinterpret_cast<const float4*>(s_x + rh * D_);
        float4 l0 = pl[0], l1 = pl[1];
        float4 h0 = ph[0], h1 = ph[1];
        xp[u][0] = pack2(l0.x, h0.x); xp[u][1] = pack2(l0.y, h0.y);
        xp[u][2] = pack2(l0.z, h0.z); xp[u][3] = pack2(l0.w, h0.w);
        xp[u][4] = pack2(l1.x, h1.x); xp[u][5] = pack2(l1.y, h1.y);
        xp[u][6] = pack2(l1.z, h1.z); xp[u][7] = pack2(l1.w, h1.w);
    }

    const ull EPS2 = 0x33D6BF9533D6BF95ull;   // (1e-7f, 1e-7f)
    ull p[NPAIR];
#pragma unroll
    for (int u = 0; u < NPAIR; u++) p[u] = 0ull;

#pragma unroll 1   // keep k-loop rolled: body fits L0 I-cache
    for (int k = 0; k < K_; k++) {
        const ulonglong2* qk  = s_q  + k * 32;
        const ulonglong2* cnk = s_cn + k * D_;
        ull prod[NPAIR];
#pragma unroll
        for (int j = 0; j < D_; j++) {
            ulonglong2 cn = cnk[j];
            ull y[NPAIR];
#pragma unroll
            for (int u = 0; u < NPAIR; u++) y[u] = cn.x;
#pragma unroll
            for (int ii = 0; ii < 4; ii++) {
                ulonglong2 q2 = qk[j * 4 + ii];      // q[2ii][j], q[2ii+1][j] (dup pairs)
#pragma unroll
                for (int u = 0; u < NPAIR; u++) y[u] = fma2(xp[u][2 * ii],     q2.x, y[u]);
#pragma unroll
                for (int u = 0; u < NPAIR; u++) y[u] = fma2(xp[u][2 * ii + 1], q2.y, y[u]);
            }
#pragma unroll
            for (int u = 0; u < NPAIR; u++) {
                ull z = mul2(y[u], y[u]);
                float zl, zh; unpack2(z, zl, zh);
                ull e = pack2(ex2f(-zl), ex2f(-zh));
                ull g = fma2(cn.y, e, EPS2);
                prod[u] = (j == 0) ? g : mul2(prod[u], g);
            }
        }
        ull wk = s_w[k];
#pragma unroll
        for (int u = 0; u < NPAIR; u++) p[u] = fma2(wk, prod[u], p[u]);
    }

    // coalesced transposed store
#pragma unroll
    for (int u = 0; u < NPAIR; u++) {
        float rl, rh; unpack2(p[u], rl, rh);
        int il = tid + (2 * u) * NTHR, ih = il + NTHR;
        if (il < valid) g_outT[(size_t)t * B + (b0 + il)] = rl;
        if (ih < valid) g_outT[(size_t)t * B + (b0 + ih)] = rh;
    }
}

// ---------------- transpose: outT[t][b] -> out[b][t] ----------------
__global__ void __launch_bounds__(256) transpose_kernel(float* __restrict__ out, int B) {
    __shared__ float tile[32][33];
    const int bb = blockIdx.x * 32;
    const int tt = blockIdx.y * 32;
    const int tx = threadIdx.x;        // 32
    const int ty = threadIdx.y;        // 8

#pragma unroll
    for (int j = 0; j < 4; j++) {
        int t = tt + ty + j * 8;
        int b = bb + tx;
        if (b < B) tile[ty + j * 8][tx] = g_outT[(size_t)t * B + b];   // coalesced in b
    }
    __syncthreads();
#pragma unroll
    for (int j = 0; j < 4; j++) {
        int b = bb + ty + j * 8;
        int t = tt + tx;
        if (b < B) out[(size_t)b * T_ + t] = tile[tx][ty + j * 8];     // coalesced in t
    }
}

// ---------------- launch ----------------
extern "C" void kernel_launch(void* const* d_in, const int* in_sizes, int n_in,
                              void* d_out, int out_size) {
    const float* x       = (const float*)d_in[0];
    const float* centers = (const float*)d_in[1];
    const float* wl      = (const float*)d_in[2];
    const float* lv      = (const float*)d_in[3];
    const float* cov     = (const float*)d_in[4];
    float* out = (float*)d_out;

    int B = in_sizes[0] / (T_ * D_);

    prep_kernel<<<(T_ * K_ * 8) / 256, 256>>>(cov, centers, wl, lv);

    dim3 grid((B + BTILE - 1) / BTILE, T_);
    pdf_kernel<<<grid, NTHR>>>(x, B);

    dim3 tgrid((B + 31) / 32, T_ / 32);
    transpose_kernel<<<tgrid, dim3(32, 8)>>>(out, B);
}